// round 5
// baseline (speedup 1.0000x reference)
#include <cuda_runtime.h>
#include <math.h>
#include <stdint.h>

#define BATCH 16
#define SEQ   2048
#define DIM   128
#define MTOT  (BATCH * SEQ)

// block geometry
#define SUPBLK_F 4608u          // floats per support/x block: 128 rows x 36 (32k + pad)
#define ACTBLK_P 4224u          // float2 per activation tile-block: 128 rows x 33 (32+pad)
#define WGTBLK_P 4128u          // float2 per weight/spmm-B block: 32 k x 129 (128+pad)

// ---------------- scratch (allocation-free device globals) ----------------
__device__ float  g_h [MTOT * DIM];                      // h exact fp32
__device__ float  g_z [MTOT * DIM];                      // z exact fp32
__device__ float  g_supb[(size_t)16384 * SUPBLK_F];      // support, tile-blocked fp32
__device__ float  g_xb  [(size_t)1024  * SUPBLK_F];      // x, tile-blocked fp32
__device__ float2 g_wgt [(size_t)28    * WGTBLK_P];      // 7 weights split hi/lo
__device__ float2 g_aact [(size_t)1024 * ACTBLK_P];      // a   split, ACT layout
__device__ float2 g_hact [(size_t)1024 * ACTBLK_P];      // h   split, ACT layout
__device__ float2 g_roact[(size_t)1024 * ACTBLK_P];      // r*h split, ACT layout
__device__ float2 g_hspb [(size_t)1024 * WGTBLK_P];      // h   split, spmm-B layout

__device__ __forceinline__ float sigmoidf_(float v) {
    return 1.0f / (1.0f + __expf(-v));
}
__device__ __forceinline__ uint32_t smem_u32(const void* p) {
    uint32_t a;
    asm("{ .reg .u64 t; cvta.to.shared.u64 t, %1; cvt.u32.u64 %0, t; }" : "=r"(a) : "l"(p));
    return a;
}
__device__ __forceinline__ uint32_t cvt_tf32(float x) {
    uint32_t u;
    asm("cvt.rna.tf32.f32 %0, %1;" : "=r"(u) : "f"(x));
    return u;
}
__device__ __forceinline__ void split_tf32(float x, uint32_t& hi, uint32_t& lo) {
    hi = cvt_tf32(x);
    lo = cvt_tf32(x - __uint_as_float(hi));
}
__device__ __forceinline__ float2 split2(float v) {
    uint32_t hi, lo;
    split_tf32(v, hi, lo);
    return make_float2(__uint_as_float(hi), __uint_as_float(lo));
}
__device__ __forceinline__ void mma_tf32(float* d, const uint32_t* a,
                                         uint32_t b0, uint32_t b1) {
    asm volatile("mma.sync.aligned.m16n8k8.row.col.f32.tf32.tf32.f32 "
                 "{%0,%1,%2,%3}, {%4,%5,%6,%7}, {%8,%9}, {%0,%1,%2,%3};"
                 : "+f"(d[0]), "+f"(d[1]), "+f"(d[2]), "+f"(d[3])
                 : "r"(a[0]), "r"(a[1]), "r"(a[2]), "r"(a[3]), "r"(b0), "r"(b1));
}
// ---- bulk copy + mbarrier (base sm_90 PTX) ----
__device__ __forceinline__ void bulk_g2s(uint32_t dst, const void* src,
                                         uint32_t bytes, uint32_t mbar) {
    asm volatile("cp.async.bulk.shared::cluster.global.mbarrier::complete_tx::bytes "
                 "[%0], [%1], %2, [%3];"
                 :: "r"(dst), "l"(src), "r"(bytes), "r"(mbar) : "memory");
}
__device__ __forceinline__ void mbar_init(uint32_t mbar, uint32_t cnt) {
    asm volatile("mbarrier.init.shared.b64 [%0], %1;" :: "r"(mbar), "r"(cnt) : "memory");
}
__device__ __forceinline__ void mbar_expect(uint32_t mbar, uint32_t bytes) {
    asm volatile("mbarrier.arrive.expect_tx.shared.b64 _, [%0], %1;"
                 :: "r"(mbar), "r"(bytes) : "memory");
}
#define MBAR_WAIT(mbar, par) do {                                                         \
    uint32_t _m = (uint32_t)(mbar);  uint32_t _p = (uint32_t)(par);  uint32_t _done;      \
    asm volatile("{\n\t.reg .pred p;\n\t"                                                 \
        "mbarrier.try_wait.parity.acquire.cta.shared::cta.b64 p, [%1], %2;\n\t"           \
        "selp.b32 %0, 1, 0, p;\n\t}" : "=r"(_done) : "r"(_m), "r"(_p) : "memory");        \
    if (!_done) {                                                                         \
        asm volatile("{\n\t.reg .pred P1;\n\t"                                            \
            "WL_%=:\n\t"                                                                  \
            "mbarrier.try_wait.parity.acquire.cta.shared::cta.b64 P1, [%0], %1, 0x989680;\n\t" \
            "@P1 bra.uni WD_%=;\n\t"                                                      \
            "bra.uni WL_%=;\n\t"                                                          \
            "WD_%=:\n\t}" :: "r"(_m), "r"(_p) : "memory");                                \
    } } while (0)

// ---- split-layout writers (used in producer epilogues) ----
__device__ __forceinline__ void store_act(float2* base, size_t row, int dim, float v) {
    base[((row >> 7) * 4 + (dim >> 5)) * (size_t)ACTBLK_P + (row & 127) * 33 + (dim & 31)]
        = split2(v);
}
__device__ __forceinline__ void store_spb(float2* base, size_t row, int dim, float v) {
    base[(row >> 5) * (size_t)WGTBLK_P + (row & 31) * 129 + dim] = split2(v);
}

// ---------------------------------------------------------------------------
// BIG kernel: 128x128 tile, A = fp32 blocks (pitch 36, split in-loop),
//             B = pre-split float2 blocks (pitch 129).
// MODE 0: encode  relu(v + b1);  writes OutF + OutAct + OutSpb; NC=4
// MODE 4: spmm    v*(1+ffd);     writes OutAct;                  NC=64
// ---------------------------------------------------------------------------
template<int MODE>
__global__ void __launch_bounds__(256, 2)
gemm_big(const float* __restrict__ Asrc0, const float2* __restrict__ Bsrc0,
         const float* __restrict__ bias1, const float* __restrict__ ffd,
         float* __restrict__ OutF, float2* __restrict__ OutAct,
         float2* __restrict__ OutSpb)
{
    constexpr int      NC     = (MODE == 4) ? 64 : 4;
    constexpr uint32_t ABYTES = SUPBLK_F * 4;   // 18432
    constexpr uint32_t BBYTES = WGTBLK_P * 8;   // 33024
    extern __shared__ float smem[];
    const uint32_t sb = smem_u32(smem);
    const uint32_t A0 = 1024u, A1 = 1024u + ABYTES;
    const uint32_t B0 = 1024u + 2 * ABYTES, B1 = B0 + BBYTES;

    const int tid = threadIdx.x, lane = tid & 31, warp = tid >> 5;
    const int wm = warp & 3, wn = warp >> 2;
    const int mbase = wm * 32, nbase = wn * 64;
    const int lq = lane >> 2, lt = lane & 3;

    const size_t rowTile = (MODE == 4)
        ? ((size_t)blockIdx.y * SEQ + (size_t)blockIdx.x * 128)
        : ((size_t)blockIdx.x * 128);
    const float* Abase = (MODE == 4)
        ? (Asrc0 + (size_t)((blockIdx.y * 16 + blockIdx.x) * 64) * SUPBLK_F)
        : (Asrc0 + (size_t)blockIdx.x * 4 * SUPBLK_F);
    const float2* Bbase = (MODE == 4)
        ? (Bsrc0 + (size_t)blockIdx.y * 64 * WGTBLK_P) : Bsrc0;

    if (tid == 0) { mbar_init(sb + 0, 1); mbar_init(sb + 8, 1); }
    __syncthreads();

    auto issue = [&](int c) {
        if (tid == 0) {
            const int buf = c & 1;
            const uint32_t mb = sb + buf * 8;
            mbar_expect(mb, ABYTES + BBYTES);
            bulk_g2s(sb + (buf ? A1 : A0), Abase + (size_t)c * SUPBLK_F, ABYTES, mb);
            bulk_g2s(sb + (buf ? B1 : B0), Bbase + (size_t)c * WGTBLK_P, BBYTES, mb);
        }
    };

    float acc[2][8][4];
#pragma unroll
    for (int mi = 0; mi < 2; mi++)
#pragma unroll
        for (int j = 0; j < 8; j++)
#pragma unroll
            for (int q = 0; q < 4; q++) acc[mi][j][q] = 0.0f;

    issue(0);
#pragma unroll 1
    for (int c = 0; c < NC; ++c) {
        if (c + 1 < NC) issue(c + 1);
        MBAR_WAIT(sb + (c & 1) * 8, (c >> 1) & 1);
        const float*  Ab = (const float*)((const char*)smem + ((c & 1) ? A1 : A0));
        const float2* Bb = (const float2*)((const char*)smem + ((c & 1) ? B1 : B0));

#pragma unroll
        for (int kk = 0; kk < 32; kk += 8) {
            uint32_t ah[2][4], al[2][4];
#pragma unroll
            for (int mi = 0; mi < 2; mi++) {
                const int m0 = mbase + mi * 16;
                split_tf32(Ab[(m0 +     lq) * 36 + kk +     lt], ah[mi][0], al[mi][0]);
                split_tf32(Ab[(m0 + 8 + lq) * 36 + kk +     lt], ah[mi][1], al[mi][1]);
                split_tf32(Ab[(m0 +     lq) * 36 + kk + 4 + lt], ah[mi][2], al[mi][2]);
                split_tf32(Ab[(m0 + 8 + lq) * 36 + kk + 4 + lt], ah[mi][3], al[mi][3]);
            }
#pragma unroll
            for (int j = 0; j < 8; j++) {
                const int n = nbase + j * 8 + lq;
                const float2 q0 = Bb[(kk +     lt) * 129 + n];
                const float2 q1 = Bb[(kk + 4 + lt) * 129 + n];
                const uint32_t bh0 = __float_as_uint(q0.x), bl0 = __float_as_uint(q0.y);
                const uint32_t bh1 = __float_as_uint(q1.x), bl1 = __float_as_uint(q1.y);
#pragma unroll
                for (int mi = 0; mi < 2; mi++) {
                    mma_tf32(acc[mi][j], ah[mi], bh0, bh1);
                    mma_tf32(acc[mi][j], ah[mi], bl0, bl1);
                    mma_tf32(acc[mi][j], al[mi], bh0, bh1);
                }
            }
        }
        __syncthreads();
    }

    // epilogue
#pragma unroll
    for (int mi = 0; mi < 2; mi++) {
        const int rA = mbase + mi * 16 + lq;
        const size_t gr0 = rowTile + rA, gr1 = gr0 + 8;
        float s0 = 1.0f, s1 = 1.0f;
        if (MODE == 4) { s0 += ffd[gr0]; s1 += ffd[gr1]; }
#pragma unroll
        for (int j = 0; j < 8; j++) {
            const int col = nbase + j * 8 + lt * 2;
#pragma unroll
            for (int q = 0; q < 4; q++) {
                const int cc = col + (q & 1);
                const size_t gr = (q < 2) ? gr0 : gr1;
                float v = acc[mi][j][q];
                if (MODE == 0) v = fmaxf(v + bias1[cc], 0.0f);
                else           v = v * ((q < 2) ? s0 : s1);
                if (OutF)   OutF[gr * 128 + cc] = v;
                if (OutAct) store_act(OutAct, gr, cc, v);
                if (OutSpb) store_spb(OutSpb, gr, cc, v);
            }
        }
    }
}

// ---------------------------------------------------------------------------
// GATE kernel: 64x128 tile, dual K=128+128, A = pre-split ACT blocks (pitch 33),
//              B = pre-split weight blocks (pitch 129). Zero in-loop cvt.
// MODE 1: sigmoid(v + b1 + b2)                 -> OutF (z)
// MODE 2: sigmoid(v + b1 + b2) * E1            -> OutAct (ro)
// MODE 3: relu(v + b1 + b2)*E2 + E1*(1-E2)     -> OutF (+OutAct/OutSpb)
// ---------------------------------------------------------------------------
template<int MODE>
__global__ void __launch_bounds__(256, 2)
gemm_gate(const float2* __restrict__ A1b, const float2* __restrict__ A2b,
          const float2* __restrict__ W1b, const float2* __restrict__ W2b,
          const float* __restrict__ bias1, const float* __restrict__ bias2,
          const float* __restrict__ E1, const float* __restrict__ E2,
          float* __restrict__ OutF, float2* __restrict__ OutAct,
          float2* __restrict__ OutSpb)
{
    constexpr int      NC     = 8;
    constexpr uint32_t ABYTES = 64 * 33 * 8;    // 16896 (64-row half block)
    constexpr uint32_t BBYTES = WGTBLK_P * 8;   // 33024
    extern __shared__ float smem[];
    const uint32_t sb = smem_u32(smem);
    const uint32_t A0 = 1024u, A1 = 1024u + ABYTES;
    const uint32_t B0 = 1024u + 2 * ABYTES, B1 = B0 + BBYTES;

    const int tid = threadIdx.x, lane = tid & 31, warp = tid >> 5;
    const int wm = warp & 1, wn = warp >> 1;
    const int mbase = wm * 32, nbase = wn * 32;
    const int lq = lane >> 2, lt = lane & 3;

    const int tile128 = blockIdx.x >> 1;
    const int half    = blockIdx.x & 1;
    const size_t rowTile = (size_t)blockIdx.x * 64;

    if (tid == 0) { mbar_init(sb + 0, 1); mbar_init(sb + 8, 1); }
    __syncthreads();

    auto issue = [&](int c) {
        if (tid == 0) {
            const int buf = c & 1;
            const int seg = c >> 2, cc = c & 3;
            const float2* As = (seg ? A2b : A1b)
                + ((size_t)tile128 * 4 + cc) * ACTBLK_P + (size_t)half * (64 * 33);
            const float2* Bs = (seg ? W2b : W1b) + (size_t)cc * WGTBLK_P;
            const uint32_t mb = sb + buf * 8;
            mbar_expect(mb, ABYTES + BBYTES);
            bulk_g2s(sb + (buf ? A1 : A0), As, ABYTES, mb);
            bulk_g2s(sb + (buf ? B1 : B0), Bs, BBYTES, mb);
        }
    };

    float acc[2][4][4];
#pragma unroll
    for (int mi = 0; mi < 2; mi++)
#pragma unroll
        for (int j = 0; j < 4; j++)
#pragma unroll
            for (int q = 0; q < 4; q++) acc[mi][j][q] = 0.0f;

    issue(0);
#pragma unroll 1
    for (int c = 0; c < NC; ++c) {
        if (c + 1 < NC) issue(c + 1);
        MBAR_WAIT(sb + (c & 1) * 8, (c >> 1) & 1);
        const float2* Ab = (const float2*)((const char*)smem + ((c & 1) ? A1 : A0));
        const float2* Bb = (const float2*)((const char*)smem + ((c & 1) ? B1 : B0));

#pragma unroll
        for (int kk = 0; kk < 32; kk += 8) {
            uint32_t ah[2][4], al[2][4];
#pragma unroll
            for (int mi = 0; mi < 2; mi++) {
                const int m0 = mbase + mi * 16;
                float2 p;
                p = Ab[(m0 +     lq) * 33 + kk +     lt]; ah[mi][0] = __float_as_uint(p.x); al[mi][0] = __float_as_uint(p.y);
                p = Ab[(m0 + 8 + lq) * 33 + kk +     lt]; ah[mi][1] = __float_as_uint(p.x); al[mi][1] = __float_as_uint(p.y);
                p = Ab[(m0 +     lq) * 33 + kk + 4 + lt]; ah[mi][2] = __float_as_uint(p.x); al[mi][2] = __float_as_uint(p.y);
                p = Ab[(m0 + 8 + lq) * 33 + kk + 4 + lt]; ah[mi][3] = __float_as_uint(p.x); al[mi][3] = __float_as_uint(p.y);
            }
#pragma unroll
            for (int j = 0; j < 4; j++) {
                const int n = nbase + j * 8 + lq;
                const float2 q0 = Bb[(kk +     lt) * 129 + n];
                const float2 q1 = Bb[(kk + 4 + lt) * 129 + n];
                const uint32_t bh0 = __float_as_uint(q0.x), bl0 = __float_as_uint(q0.y);
                const uint32_t bh1 = __float_as_uint(q1.x), bl1 = __float_as_uint(q1.y);
#pragma unroll
                for (int mi = 0; mi < 2; mi++) {
                    mma_tf32(acc[mi][j], ah[mi], bh0, bh1);
                    mma_tf32(acc[mi][j], ah[mi], bl0, bl1);
                    mma_tf32(acc[mi][j], al[mi], bh0, bh1);
                }
            }
        }
        __syncthreads();
    }

    // epilogue
#pragma unroll
    for (int mi = 0; mi < 2; mi++) {
        const int rA = mbase + mi * 16 + lq;
        const size_t gr0 = rowTile + rA, gr1 = gr0 + 8;
#pragma unroll
        for (int j = 0; j < 4; j++) {
            const int col = nbase + j * 8 + lt * 2;
#pragma unroll
            for (int q = 0; q < 4; q++) {
                const int cc = col + (q & 1);
                const size_t gr = (q < 2) ? gr0 : gr1;
                float v = acc[mi][j][q] + bias1[cc] + bias2[cc];
                if (MODE == 1) {
                    v = sigmoidf_(v);
                } else if (MODE == 2) {
                    v = sigmoidf_(v) * E1[gr * 128 + cc];
                } else {
                    const float zz = E2[gr * 128 + cc];
                    const float hp = E1[gr * 128 + cc];
                    v = fmaxf(v, 0.0f) * zz + hp * (1.0f - zz);
                }
                if (OutF)   OutF[gr * 128 + cc] = v;
                if (OutAct) store_act(OutAct, gr, cc, v);
                if (OutSpb) store_spb(OutSpb, gr, cc, v);
            }
        }
    }
}

// ---------------------------------------------------------------------------
// repack: support fp32 [b][m][2048] -> blocks [(b*16+mt)*64+ch][128][36]
// ---------------------------------------------------------------------------
__global__ void __launch_bounds__(128)
repack_sup(const float* __restrict__ S, float* __restrict__ out)
{
    const int ch = blockIdx.x, mt = blockIdx.y, b = blockIdx.z;
    const int r = threadIdx.x;
    const float* src = S + ((size_t)(b * 2048 + mt * 128 + r)) * 2048 + ch * 32;
    float* dst = out + ((size_t)((b * 16 + mt) * 64 + ch)) * SUPBLK_F + r * 36;
#pragma unroll
    for (int g = 0; g < 8; g++)
        *(float4*)(dst + g * 4) = *(const float4*)(src + g * 4);
}

// x fp32 [row][128] -> blocks [tile*4+ch][128][36]
__global__ void __launch_bounds__(128)
repack_x(const float* __restrict__ X, float* __restrict__ out)
{
    const int ch = blockIdx.x, tile = blockIdx.y;
    const int r = threadIdx.x;
    const float* src = X + ((size_t)(tile * 128 + r)) * 128 + ch * 32;
    float* dst = out + ((size_t)(tile * 4 + ch)) * SUPBLK_F + r * 36;
#pragma unroll
    for (int g = 0; g < 8; g++)
        *(float4*)(dst + g * 4) = *(const float4*)(src + g * 4);
}

// weights [k=128][n=128] -> split blocks [m*4+ch][32][129] float2
__global__ void __launch_bounds__(256)
split_wgt(const float* __restrict__ w0, const float* __restrict__ w1,
          const float* __restrict__ w2, const float* __restrict__ w3,
          const float* __restrict__ w4, const float* __restrict__ w5,
          const float* __restrict__ w6, float2* __restrict__ out)
{
    const int ch = blockIdx.x, m = blockIdx.y;
    const float* W;
    switch (m) {
        case 0: W = w0; break; case 1: W = w1; break; case 2: W = w2; break;
        case 3: W = w3; break; case 4: W = w4; break; case 5: W = w5; break;
        default: W = w6; break;
    }
    float2* dst = out + ((size_t)m * 4 + ch) * WGTBLK_P;
    for (int idx = threadIdx.x; idx < 32 * 128; idx += 256) {
        const int kr = idx >> 7, n = idx & 127;
        dst[kr * 129 + n] = split2(W[(ch * 32 + kr) * 128 + n]);
    }
}

extern "C" void kernel_launch(void* const* d_in, const int* in_sizes, int n_in,
                              void* d_out, int out_size)
{
    const float* x       = (const float*)d_in[0];
    const float* support = (const float*)d_in[1];
    const float* ffd     = (const float*)d_in[2];
    // d_in[3] = mask (unused by reference)
    const float* We  = (const float*)d_in[4];
    const float* be  = (const float*)d_in[5];
    const float* Wz0 = (const float*)d_in[6];
    const float* bz0 = (const float*)d_in[7];
    const float* Wz1 = (const float*)d_in[8];
    const float* bz1 = (const float*)d_in[9];
    const float* Wr0 = (const float*)d_in[10];
    const float* br0 = (const float*)d_in[11];
    const float* Wr1 = (const float*)d_in[12];
    const float* br1 = (const float*)d_in[13];
    const float* Wh0 = (const float*)d_in[14];
    const float* bh0 = (const float*)d_in[15];
    const float* Wh1 = (const float*)d_in[16];
    const float* bh1 = (const float*)d_in[17];

    float *h, *z, *supb, *xb;
    float2 *wgt, *aact, *hact, *roact, *hspb;
    cudaGetSymbolAddress((void**)&h,     g_h);
    cudaGetSymbolAddress((void**)&z,     g_z);
    cudaGetSymbolAddress((void**)&supb,  g_supb);
    cudaGetSymbolAddress((void**)&xb,    g_xb);
    cudaGetSymbolAddress((void**)&wgt,   g_wgt);
    cudaGetSymbolAddress((void**)&aact,  g_aact);
    cudaGetSymbolAddress((void**)&hact,  g_hact);
    cudaGetSymbolAddress((void**)&roact, g_roact);
    cudaGetSymbolAddress((void**)&hspb,  g_hspb);

    const float2* WeB  = wgt + (size_t)0 * 4 * WGTBLK_P;
    const float2* Wz0B = wgt + (size_t)1 * 4 * WGTBLK_P;
    const float2* Wz1B = wgt + (size_t)2 * 4 * WGTBLK_P;
    const float2* Wr0B = wgt + (size_t)3 * 4 * WGTBLK_P;
    const float2* Wr1B = wgt + (size_t)4 * 4 * WGTBLK_P;
    const float2* Wh0B = wgt + (size_t)5 * 4 * WGTBLK_P;
    const float2* Wh1B = wgt + (size_t)6 * 4 * WGTBLK_P;

    const int SMB = 1024 + 2 * (SUPBLK_F * 4) + 2 * (WGTBLK_P * 8);   // 103936
    const int SMG = 1024 + 2 * (64 * 33 * 8)  + 2 * (WGTBLK_P * 8);   // 100864
    cudaFuncSetAttribute(gemm_big<0>,  cudaFuncAttributeMaxDynamicSharedMemorySize, SMB);
    cudaFuncSetAttribute(gemm_big<4>,  cudaFuncAttributeMaxDynamicSharedMemorySize, SMB);
    cudaFuncSetAttribute(gemm_gate<1>, cudaFuncAttributeMaxDynamicSharedMemorySize, SMG);
    cudaFuncSetAttribute(gemm_gate<2>, cudaFuncAttributeMaxDynamicSharedMemorySize, SMG);
    cudaFuncSetAttribute(gemm_gate<3>, cudaFuncAttributeMaxDynamicSharedMemorySize, SMG);

    // one-time repacks / splits
    repack_sup<<<dim3(64, 16, 16), 128>>>(support, supb);
    repack_x  <<<dim3(4, 256),     128>>>(x, xb);
    split_wgt <<<dim3(4, 7),       256>>>(We, Wz0, Wz1, Wr0, Wr1, Wh0, Wh1, wgt);

    // h = relu(x @ We + be)
    gemm_big<0><<<256, 256, SMB>>>(xb, WeB, be, nullptr, h, hact, hspb);

    for (int t = 0; t < 2; ++t) {
        // a = (support @ h) * (1 + FFD)
        gemm_big<4><<<dim3(16, 16), 256, SMB>>>(supb, hspb, nullptr, ffd,
                                                nullptr, aact, nullptr);
        // z = sigmoid(a@Wz0 + h@Wz1 + bz)
        gemm_gate<1><<<512, 256, SMG>>>(aact, hact, Wz0B, Wz1B, bz0, bz1,
                                        nullptr, nullptr, z, nullptr, nullptr);
        // ro = sigmoid(a@Wr0 + h@Wr1 + br) * h
        gemm_gate<2><<<512, 256, SMG>>>(aact, hact, Wr0B, Wr1B, br0, br1,
                                        h, nullptr, nullptr, roact, nullptr);
        // h' = relu(a@Wh0 + ro@Wh1 + bh)*z + h*(1-z)
        gemm_gate<3><<<512, 256, SMG>>>(aact, roact, Wh0B, Wh1B, bh0, bh1,
                                        h, z,
                                        (t == 1) ? (float*)d_out : h,
                                        (t == 1) ? nullptr : hact,
                                        (t == 1) ? nullptr : hspb);
    }
}

// round 6
// speedup vs baseline: 1.6071x; 1.6071x over previous
#include <cuda_runtime.h>
#include <cuda.h>
#include <math.h>
#include <stdint.h>

#define BATCH 16
#define SEQ   2048
#define DIM   128
#define MTOT  (BATCH * SEQ)

// ---------------- scratch (allocation-free device globals) ----------------
__device__ float g_h [MTOT * DIM];
__device__ float g_a [MTOT * DIM];
__device__ float g_z [MTOT * DIM];
__device__ float g_ro[MTOT * DIM];

__device__ __forceinline__ float sigmoidf_(float v) {
    return 1.0f / (1.0f + __expf(-v));
}
__device__ __forceinline__ uint32_t smem_u32(const void* p) {
    uint32_t a;
    asm("{ .reg .u64 t; cvta.to.shared.u64 t, %1; cvt.u32.u64 %0, t; }" : "=r"(a) : "l"(p));
    return a;
}
__device__ __forceinline__ uint32_t cvt_tf32(float x) {
    uint32_t u;
    asm("cvt.rna.tf32.f32 %0, %1;" : "=r"(u) : "f"(x));
    return u;
}
__device__ __forceinline__ void split_tf32(float x, uint32_t& hi, uint32_t& lo) {
    hi = cvt_tf32(x);
    lo = cvt_tf32(x - __uint_as_float(hi));
}
__device__ __forceinline__ void mma_tf32(float* d, const uint32_t* a,
                                         uint32_t b0, uint32_t b1) {
    asm volatile("mma.sync.aligned.m16n8k8.row.col.f32.tf32.tf32.f32 "
                 "{%0,%1,%2,%3}, {%4,%5,%6,%7}, {%8,%9}, {%0,%1,%2,%3};"
                 : "+f"(d[0]), "+f"(d[1]), "+f"(d[2]), "+f"(d[3])
                 : "r"(a[0]), "r"(a[1]), "r"(a[2]), "r"(a[3]), "r"(b0), "r"(b1));
}
// ---- TMA + mbarrier (base sm_90 PTX, per examples/test_tma.cu) ----
__device__ __forceinline__ void tma2d(uint32_t dst, const void* map,
                                      int c0, int c1, uint32_t mbar) {
    asm volatile("cp.async.bulk.tensor.2d.shared::cta.global.tile.mbarrier::complete_tx::bytes "
                 "[%0], [%1, {%2, %3}], [%4];"
                 :: "r"(dst), "l"(map), "r"(c0), "r"(c1), "r"(mbar) : "memory");
}
__device__ __forceinline__ void tma3d(uint32_t dst, const void* map,
                                      int c0, int c1, int c2, uint32_t mbar) {
    asm volatile("cp.async.bulk.tensor.3d.shared::cta.global.tile.mbarrier::complete_tx::bytes "
                 "[%0], [%1, {%2, %3, %4}], [%5];"
                 :: "r"(dst), "l"(map), "r"(c0), "r"(c1), "r"(c2), "r"(mbar) : "memory");
}
__device__ __forceinline__ void mbar_init(uint32_t mbar, uint32_t cnt) {
    asm volatile("mbarrier.init.shared.b64 [%0], %1;" :: "r"(mbar), "r"(cnt) : "memory");
}
__device__ __forceinline__ void mbar_expect(uint32_t mbar, uint32_t bytes) {
    asm volatile("mbarrier.arrive.expect_tx.shared.b64 _, [%0], %1;"
                 :: "r"(mbar), "r"(bytes) : "memory");
}
__device__ __forceinline__ void mbar_wait(uint32_t mbar, uint32_t parity) {
    uint32_t done;
    asm volatile("{\n\t.reg .pred p;\n\t"
                 "mbarrier.try_wait.parity.acquire.cta.shared::cta.b64 p, [%1], %2;\n\t"
                 "selp.b32 %0, 1, 0, p;\n\t}"
                 : "=r"(done) : "r"(mbar), "r"(parity) : "memory");
    while (!done) {
        asm volatile("{\n\t.reg .pred p;\n\t"
                     "mbarrier.try_wait.parity.acquire.cta.shared::cta.b64 p, [%1], %2;\n\t"
                     "selp.b32 %0, 1, 0, p;\n\t}"
                     : "=r"(done) : "r"(mbar), "r"(parity) : "memory");
    }
}

#define NSTAGE     3
#define STAGE_B    32768u              // A 16KB + B 16KB
#define DATA_OFF   1024u
#define SMEM_BYTES (DATA_OFF + NSTAGE * STAGE_B)   // 99328

// ---------------------------------------------------------------------------
// Unified TMA + 3xTF32 GEMM, 128x128 tile, 256 threads, 3-stage pipeline.
// C = epilogue( A1 @ B1 (+ A2 @ B2) + bias )
// MODE 0: relu(v + b1)
// MODE 1: sigmoid(v + b1 + b2)
// MODE 2: sigmoid(v + b1 + b2) * E1
// MODE 3: relu(v + b1 + b2)*E2 + E1*(1-E2)
// MODE 4: v * (1 + ffd[row])                      (spmm)
// SMEM tiles are SW128-swizzled by TMA; fragment reads apply the XOR manually.
// ---------------------------------------------------------------------------
template<int MODE, bool DUAL, bool SPMM, int K>
__global__ void __launch_bounds__(256, 2)
gemm_tma(const __grid_constant__ CUtensorMap mA1,
         const __grid_constant__ CUtensorMap mB1,
         const __grid_constant__ CUtensorMap mA2,
         const __grid_constant__ CUtensorMap mB2,
         const float* __restrict__ bias1, const float* __restrict__ bias2,
         const float* __restrict__ E1, const float* __restrict__ E2,
         const float* __restrict__ ffd, float* __restrict__ Cout)
{
    extern __shared__ __align__(1024) char smem[];
    const uint32_t sb = smem_u32(smem);

    const int tid = threadIdx.x, lane = tid & 31, warp = tid >> 5;
    const int wm = warp & 3, wn = warp >> 2;
    const int mbase = wm * 32, nbase = wn * 64;
    const int lq = lane >> 2, lt = lane & 3;

    const size_t rowTile = SPMM ? ((size_t)blockIdx.y * SEQ + (size_t)blockIdx.x * 128)
                                : ((size_t)blockIdx.x * 128);
    constexpr int KCH = K / 32;
    constexpr int NC  = DUAL ? 2 * KCH : KCH;

    if (tid == 0) {
#pragma unroll
        for (int s = 0; s < NSTAGE; s++) mbar_init(sb + s * 8, 1);
    }
    __syncthreads();

    auto issue = [&](int c) {
        const int s = c % NSTAGE;
        const uint32_t bar  = sb + s * 8;
        const uint32_t dstA = sb + DATA_OFF + s * STAGE_B;
        const uint32_t dstB = dstA + 16384u;
        const bool seg = DUAL && (c >= KCH);
        const int  k0  = (seg ? c - KCH : c) * 32;
        mbar_expect(bar, STAGE_B);
        const void* mA = seg ? (const void*)&mA2 : (const void*)&mA1;
        const void* mB = seg ? (const void*)&mB2 : (const void*)&mB1;
        if (SPMM) tma3d(dstA, mA, k0, (int)(blockIdx.x * 128), (int)blockIdx.y, bar);
        else      tma2d(dstA, mA, k0, (int)(blockIdx.x * 128), bar);
        const int brow = SPMM ? (int)(blockIdx.y * SEQ + k0) : k0;
#pragma unroll
        for (int i = 0; i < 4; i++)
            tma2d(dstB + i * 4096u, mB, i * 32, brow, bar);
    };

    float acc[2][8][4];
#pragma unroll
    for (int mi = 0; mi < 2; mi++)
#pragma unroll
        for (int j = 0; j < 8; j++)
#pragma unroll
            for (int q = 0; q < 4; q++) acc[mi][j][q] = 0.0f;

    // per-thread constant swizzled byte-columns
    const uint32_t aswz = (uint32_t)lq << 4;            // (r&7)<<4, r&7 == lq
    uint32_t bcol0[8], bcol1[8];
#pragma unroll
    for (int j = 0; j < 8; j++) {
        const int n  = nbase + j * 8 + lq;
        const uint32_t nb = (uint32_t)((n & 31) * 4);
        bcol0[j] = ((uint32_t)(n >> 5)) * 4096u + (nb ^ ((uint32_t)lt << 4));
        bcol1[j] = ((uint32_t)(n >> 5)) * 4096u + (nb ^ (((uint32_t)(lt + 4)) << 4));
    }

    if (tid == 0) {
        issue(0); issue(1);
        if (NC > 2) issue(2);
    }

#pragma unroll 1
    for (int c = 0; c < NC; ++c) {
        const int s = c % NSTAGE;
        mbar_wait(sb + s * 8, (uint32_t)((c / NSTAGE) & 1));

        const char* As = smem + DATA_OFF + s * STAGE_B;
        const char* Bs = As + 16384;

#pragma unroll
        for (int kk = 0; kk < 32; kk += 8) {
            const int kt0 = kk + lt, kt1 = kt0 + 4;
            uint32_t ah[2][4], al[2][4];
#pragma unroll
            for (int mi = 0; mi < 2; mi++) {
                const int r0 = mbase + mi * 16 + lq, r1 = r0 + 8;
                const uint32_t c0 = ((uint32_t)(kt0 * 4)) ^ aswz;
                const uint32_t c1 = ((uint32_t)(kt1 * 4)) ^ aswz;
                split_tf32(*(const float*)(As + r0 * 128 + c0), ah[mi][0], al[mi][0]);
                split_tf32(*(const float*)(As + r1 * 128 + c0), ah[mi][1], al[mi][1]);
                split_tf32(*(const float*)(As + r0 * 128 + c1), ah[mi][2], al[mi][2]);
                split_tf32(*(const float*)(As + r1 * 128 + c1), ah[mi][3], al[mi][3]);
            }
#pragma unroll
            for (int j = 0; j < 8; j++) {
                uint32_t bh0, bl0, bh1, bl1;
                split_tf32(*(const float*)(Bs + kt0 * 128 + bcol0[j]), bh0, bl0);
                split_tf32(*(const float*)(Bs + kt1 * 128 + bcol1[j]), bh1, bl1);
#pragma unroll
                for (int mi = 0; mi < 2; mi++) {
                    mma_tf32(acc[mi][j], ah[mi], bh0, bh1);
                    mma_tf32(acc[mi][j], ah[mi], bl0, bl1);
                    mma_tf32(acc[mi][j], al[mi], bh0, bh1);
                }
            }
        }
        __syncthreads();
        if (c + NSTAGE < NC && tid == 0) issue(c + NSTAGE);
    }

    // ---- epilogue (identical to round 4) ----
#pragma unroll
    for (int mi = 0; mi < 2; mi++) {
        const int rA = mbase + mi * 16 + lq;
        const size_t gr0 = rowTile + rA, gr1 = gr0 + 8;
        float s0 = 1.0f, s1 = 1.0f;
        if (MODE == 4) { s0 += ffd[gr0]; s1 += ffd[gr1]; }
#pragma unroll
        for (int j = 0; j < 8; j++) {
            const int col = nbase + j * 8 + lt * 2;
            float o[4];
#pragma unroll
            for (int q = 0; q < 4; q++) {
                const int    cc = col + (q & 1);
                const size_t gr = (q < 2) ? gr0 : gr1;
                float v = acc[mi][j][q];
                if (MODE == 0) {
                    v = fmaxf(v + bias1[cc], 0.0f);
                } else if (MODE == 1) {
                    v = sigmoidf_(v + bias1[cc] + bias2[cc]);
                } else if (MODE == 2) {
                    v = sigmoidf_(v + bias1[cc] + bias2[cc]) * E1[gr * 128 + cc];
                } else if (MODE == 3) {
                    const float zz = E2[gr * 128 + cc];
                    const float hp = E1[gr * 128 + cc];
                    v = fmaxf(v + bias1[cc] + bias2[cc], 0.0f) * zz + hp * (1.0f - zz);
                } else {
                    v = v * ((q < 2) ? s0 : s1);
                }
                o[q] = v;
            }
            *(float2*)&Cout[gr0 * 128 + col] = make_float2(o[0], o[1]);
            *(float2*)&Cout[gr1 * 128 + col] = make_float2(o[2], o[3]);
        }
    }
}

// ---------------------------------------------------------------------------
// host side
// ---------------------------------------------------------------------------
typedef CUresult (*pfn_encode_t)(CUtensorMap*, CUtensorMapDataType, cuuint32_t,
                                 void*, const cuuint64_t*, const cuuint64_t*,
                                 const cuuint32_t*, const cuuint32_t*,
                                 CUtensorMapInterleave, CUtensorMapSwizzle,
                                 CUtensorMapL2promotion, CUtensorMapFloatOOBfill);
static pfn_encode_t enc_fn = nullptr;

static void map2d(CUtensorMap* m, const void* ptr, uint64_t d0, uint64_t d1,
                  uint32_t b0, uint32_t b1) {
    cuuint64_t dims[2]    = {d0, d1};
    cuuint64_t strides[1] = {d0 * 4};
    cuuint32_t box[2]     = {b0, b1};
    cuuint32_t es[2]      = {1, 1};
    enc_fn(m, CU_TENSOR_MAP_DATA_TYPE_FLOAT32, 2, (void*)ptr, dims, strides, box, es,
           CU_TENSOR_MAP_INTERLEAVE_NONE, CU_TENSOR_MAP_SWIZZLE_128B,
           CU_TENSOR_MAP_L2_PROMOTION_L2_128B, CU_TENSOR_MAP_FLOAT_OOB_FILL_NONE);
}
static void map3d_sup(CUtensorMap* m, const void* ptr) {
    cuuint64_t dims[3]    = {SEQ, SEQ, BATCH};
    cuuint64_t strides[2] = {(uint64_t)SEQ * 4, (uint64_t)SEQ * SEQ * 4};
    cuuint32_t box[3]     = {32, 128, 1};
    cuuint32_t es[3]      = {1, 1, 1};
    enc_fn(m, CU_TENSOR_MAP_DATA_TYPE_FLOAT32, 3, (void*)ptr, dims, strides, box, es,
           CU_TENSOR_MAP_INTERLEAVE_NONE, CU_TENSOR_MAP_SWIZZLE_128B,
           CU_TENSOR_MAP_L2_PROMOTION_L2_128B, CU_TENSOR_MAP_FLOAT_OOB_FILL_NONE);
}

extern "C" void kernel_launch(void* const* d_in, const int* in_sizes, int n_in,
                              void* d_out, int out_size)
{
    const float* x       = (const float*)d_in[0];
    const float* support = (const float*)d_in[1];
    const float* ffd     = (const float*)d_in[2];
    // d_in[3] = mask (unused by reference)
    const float* We  = (const float*)d_in[4];
    const float* be  = (const float*)d_in[5];
    const float* Wz0 = (const float*)d_in[6];
    const float* bz0 = (const float*)d_in[7];
    const float* Wz1 = (const float*)d_in[8];
    const float* bz1 = (const float*)d_in[9];
    const float* Wr0 = (const float*)d_in[10];
    const float* br0 = (const float*)d_in[11];
    const float* Wr1 = (const float*)d_in[12];
    const float* br1 = (const float*)d_in[13];
    const float* Wh0 = (const float*)d_in[14];
    const float* bh0 = (const float*)d_in[15];
    const float* Wh1 = (const float*)d_in[16];
    const float* bh1 = (const float*)d_in[17];

    float *h, *a, *z, *ro;
    cudaGetSymbolAddress((void**)&h,  g_h);
    cudaGetSymbolAddress((void**)&a,  g_a);
    cudaGetSymbolAddress((void**)&z,  g_z);
    cudaGetSymbolAddress((void**)&ro, g_ro);

    if (!enc_fn) {
        cudaDriverEntryPointQueryResult qr;
        cudaGetDriverEntryPoint("cuTensorMapEncodeTiled", (void**)&enc_fn,
                                cudaEnableDefault, &qr);
    }

    // tensor maps (host-side, deterministic per call)
    CUtensorMap m_sup, m_x, m_a, m_h, m_ro, m_hB;
    CUtensorMap m_We, m_Wz0, m_Wz1, m_Wr0, m_Wr1, m_Wh0, m_Wh1;
    map3d_sup(&m_sup, support);
    map2d(&m_x,  x,  DIM, MTOT, 32, 128);
    map2d(&m_a,  a,  DIM, MTOT, 32, 128);
    map2d(&m_h,  h,  DIM, MTOT, 32, 128);
    map2d(&m_ro, ro, DIM, MTOT, 32, 128);
    map2d(&m_hB, h,  DIM, MTOT, 32, 32);
    map2d(&m_We,  We,  DIM, DIM, 32, 32);
    map2d(&m_Wz0, Wz0, DIM, DIM, 32, 32);
    map2d(&m_Wz1, Wz1, DIM, DIM, 32, 32);
    map2d(&m_Wr0, Wr0, DIM, DIM, 32, 32);
    map2d(&m_Wr1, Wr1, DIM, DIM, 32, 32);
    map2d(&m_Wh0, Wh0, DIM, DIM, 32, 32);
    map2d(&m_Wh1, Wh1, DIM, DIM, 32, 32);

    cudaFuncSetAttribute(gemm_tma<0, false, false, 128>, cudaFuncAttributeMaxDynamicSharedMemorySize, SMEM_BYTES);
    cudaFuncSetAttribute(gemm_tma<1, true,  false, 128>, cudaFuncAttributeMaxDynamicSharedMemorySize, SMEM_BYTES);
    cudaFuncSetAttribute(gemm_tma<2, true,  false, 128>, cudaFuncAttributeMaxDynamicSharedMemorySize, SMEM_BYTES);
    cudaFuncSetAttribute(gemm_tma<3, true,  false, 128>, cudaFuncAttributeMaxDynamicSharedMemorySize, SMEM_BYTES);
    cudaFuncSetAttribute(gemm_tma<4, false, true, 2048>, cudaFuncAttributeMaxDynamicSharedMemorySize, SMEM_BYTES);

    const dim3 blk(256);
    const dim3 grd_dense(MTOT / 128);          // 256
    const dim3 grd_spmm(SEQ / 128, BATCH);     // (16,16)

    // h = relu(x @ We + be)
    gemm_tma<0, false, false, 128><<<grd_dense, blk, SMEM_BYTES>>>(
        m_x, m_We, m_x, m_We, be, nullptr, nullptr, nullptr, nullptr, h);

    for (int t = 0; t < 2; ++t) {
        // a = (support @ h) * (1 + FFD)
        gemm_tma<4, false, true, 2048><<<grd_spmm, blk, SMEM_BYTES>>>(
            m_sup, m_hB, m_sup, m_hB, nullptr, nullptr, nullptr, nullptr, ffd, a);
        // z = sigmoid(a@Wz0 + h@Wz1 + bz)
        gemm_tma<1, true, false, 128><<<grd_dense, blk, SMEM_BYTES>>>(
            m_a, m_Wz0, m_h, m_Wz1, bz0, bz1, nullptr, nullptr, nullptr, z);
        // ro = sigmoid(a@Wr0 + h@Wr1 + br) * h
        gemm_tma<2, true, false, 128><<<grd_dense, blk, SMEM_BYTES>>>(
            m_a, m_Wr0, m_h, m_Wr1, br0, br1, h, nullptr, nullptr, ro);
        // h' = relu(a@Wh0 + ro@Wh1 + bh)*z + h*(1-z)
        float* dst = (t == 1) ? (float*)d_out : h;
        gemm_tma<3, true, false, 128><<<grd_dense, blk, SMEM_BYTES>>>(
            m_a, m_Wh0, m_ro, m_Wh1, bh0, bh1, h, z, nullptr, dst);
    }
}

// round 7
// speedup vs baseline: 1.8117x; 1.1273x over previous
#include <cuda_runtime.h>
#include <cuda.h>
#include <math.h>
#include <stdint.h>

#define BATCH 16
#define SEQ   2048
#define DIM   128
#define MTOT  (BATCH * SEQ)

// ---------------- scratch (allocation-free device globals) ----------------
__device__ float g_h[MTOT * DIM];
__device__ float g_a[MTOT * DIM];

__device__ __forceinline__ float sigmoidf_(float v) {
    return 1.0f / (1.0f + __expf(-v));
}
__device__ __forceinline__ uint32_t smem_u32(const void* p) {
    uint32_t a;
    asm("{ .reg .u64 t; cvta.to.shared.u64 t, %1; cvt.u32.u64 %0, t; }" : "=r"(a) : "l"(p));
    return a;
}
// truncation split: hi = top tf32 bits, lo = exact remainder (2 ops).
// mma.sync.tf32 reads bits [31:13] of the register, so no cvt needed.
__device__ __forceinline__ void tsplit(float x, uint32_t& hi, uint32_t& lo) {
    hi = __float_as_uint(x) & 0xFFFFE000u;
    lo = __float_as_uint(x - __uint_as_float(hi));
}
__device__ __forceinline__ void mma_tf32(float* d, const uint32_t* a,
                                         uint32_t b0, uint32_t b1) {
    asm volatile("mma.sync.aligned.m16n8k8.row.col.f32.tf32.tf32.f32 "
                 "{%0,%1,%2,%3}, {%4,%5,%6,%7}, {%8,%9}, {%0,%1,%2,%3};"
                 : "+f"(d[0]), "+f"(d[1]), "+f"(d[2]), "+f"(d[3])
                 : "r"(a[0]), "r"(a[1]), "r"(a[2]), "r"(a[3]), "r"(b0), "r"(b1));
}
// ---- TMA + mbarrier ----
__device__ __forceinline__ void tma2d(uint32_t dst, const void* map,
                                      int c0, int c1, uint32_t mbar) {
    asm volatile("cp.async.bulk.tensor.2d.shared::cta.global.tile.mbarrier::complete_tx::bytes "
                 "[%0], [%1, {%2, %3}], [%4];"
                 :: "r"(dst), "l"(map), "r"(c0), "r"(c1), "r"(mbar) : "memory");
}
__device__ __forceinline__ void tma3d(uint32_t dst, const void* map,
                                      int c0, int c1, int c2, uint32_t mbar) {
    asm volatile("cp.async.bulk.tensor.3d.shared::cta.global.tile.mbarrier::complete_tx::bytes "
                 "[%0], [%1, {%2, %3, %4}], [%5];"
                 :: "r"(dst), "l"(map), "r"(c0), "r"(c1), "r"(c2), "r"(mbar) : "memory");
}
__device__ __forceinline__ void mbar_init(uint32_t mbar, uint32_t cnt) {
    asm volatile("mbarrier.init.shared.b64 [%0], %1;" :: "r"(mbar), "r"(cnt) : "memory");
}
__device__ __forceinline__ void mbar_expect(uint32_t mbar, uint32_t bytes) {
    asm volatile("mbarrier.arrive.expect_tx.shared.b64 _, [%0], %1;"
                 :: "r"(mbar), "r"(bytes) : "memory");
}
__device__ __forceinline__ void mbar_wait(uint32_t mbar, uint32_t parity) {
    uint32_t done;
    asm volatile("{\n\t.reg .pred p;\n\t"
                 "mbarrier.try_wait.parity.acquire.cta.shared::cta.b64 p, [%1], %2;\n\t"
                 "selp.b32 %0, 1, 0, p;\n\t}"
                 : "=r"(done) : "r"(mbar), "r"(parity) : "memory");
    while (!done) {
        asm volatile("{\n\t.reg .pred p;\n\t"
                     "mbarrier.try_wait.parity.acquire.cta.shared::cta.b64 p, [%1], %2;\n\t"
                     "selp.b32 %0, 1, 0, p;\n\t}"
                     : "=r"(done) : "r"(mbar), "r"(parity) : "memory");
    }
}

// ===========================================================================
// Kernel 1: encode / spmm (TMA + 3xTF32), 128x128 tile, 256 threads, 3 stages
// MODE 0: relu(v + b1)         MODE 4: v * (1 + ffd[row])  (spmm)
// ===========================================================================
#define NSTAGE     3
#define STAGE_B    32768u
#define DATA_OFF   1024u
#define SMEM_BYTES (DATA_OFF + NSTAGE * STAGE_B)

template<int MODE, bool SPMM, int K>
__global__ void __launch_bounds__(256, 2)
gemm_tma(const __grid_constant__ CUtensorMap mA1,
         const __grid_constant__ CUtensorMap mB1,
         const float* __restrict__ bias1,
         const float* __restrict__ ffd, float* __restrict__ Cout)
{
    extern __shared__ __align__(1024) char smem[];
    const uint32_t sb = smem_u32(smem);

    const int tid = threadIdx.x, lane = tid & 31, warp = tid >> 5;
    const int wm = warp & 3, wn = warp >> 2;
    const int mbase = wm * 32, nbase = wn * 64;
    const int lq = lane >> 2, lt = lane & 3;

    const size_t rowTile = SPMM ? ((size_t)blockIdx.y * SEQ + (size_t)blockIdx.x * 128)
                                : ((size_t)blockIdx.x * 128);
    constexpr int NC = K / 32;

    if (tid == 0) {
#pragma unroll
        for (int s = 0; s < NSTAGE; s++) mbar_init(sb + s * 8, 1);
    }
    __syncthreads();

    auto issue = [&](int c) {
        const int s = c % NSTAGE;
        const uint32_t bar  = sb + s * 8;
        const uint32_t dstA = sb + DATA_OFF + s * STAGE_B;
        const uint32_t dstB = dstA + 16384u;
        const int k0 = c * 32;
        mbar_expect(bar, STAGE_B);
        if (SPMM) tma3d(dstA, &mA1, k0, (int)(blockIdx.x * 128), (int)blockIdx.y, bar);
        else      tma2d(dstA, &mA1, k0, (int)(blockIdx.x * 128), bar);
        const int brow = SPMM ? (int)(blockIdx.y * SEQ + k0) : k0;
#pragma unroll
        for (int i = 0; i < 4; i++)
            tma2d(dstB + i * 4096u, &mB1, i * 32, brow, bar);
    };

    float acc[2][8][4];
#pragma unroll
    for (int mi = 0; mi < 2; mi++)
#pragma unroll
        for (int j = 0; j < 8; j++)
#pragma unroll
            for (int q = 0; q < 4; q++) acc[mi][j][q] = 0.0f;

    const uint32_t aswz = (uint32_t)lq << 4;
    uint32_t bcol0[8], bcol1[8];
#pragma unroll
    for (int j = 0; j < 8; j++) {
        const int n  = nbase + j * 8 + lq;
        const uint32_t nb = (uint32_t)((n & 31) * 4);
        bcol0[j] = ((uint32_t)(n >> 5)) * 4096u + (nb ^ ((uint32_t)lt << 4));
        bcol1[j] = ((uint32_t)(n >> 5)) * 4096u + (nb ^ (((uint32_t)(lt + 4)) << 4));
    }

    if (tid == 0) {
        issue(0);
        if (NC > 1) issue(1);
        if (NC > 2) issue(2);
    }

#pragma unroll 1
    for (int c = 0; c < NC; ++c) {
        const int s = c % NSTAGE;
        mbar_wait(sb + s * 8, (uint32_t)((c / NSTAGE) & 1));
        const char* As = smem + DATA_OFF + s * STAGE_B;
        const char* Bs = As + 16384;

#pragma unroll
        for (int kk = 0; kk < 32; kk += 8) {
            const int kt0 = kk + lt, kt1 = kt0 + 4;
            uint32_t ah[2][4], al[2][4];
#pragma unroll
            for (int mi = 0; mi < 2; mi++) {
                const int r0 = mbase + mi * 16 + lq, r1 = r0 + 8;
                const uint32_t c0 = ((uint32_t)(kt0 * 4)) ^ aswz;
                const uint32_t c1 = ((uint32_t)(kt1 * 4)) ^ aswz;
                tsplit(*(const float*)(As + r0 * 128 + c0), ah[mi][0], al[mi][0]);
                tsplit(*(const float*)(As + r1 * 128 + c0), ah[mi][1], al[mi][1]);
                tsplit(*(const float*)(As + r0 * 128 + c1), ah[mi][2], al[mi][2]);
                tsplit(*(const float*)(As + r1 * 128 + c1), ah[mi][3], al[mi][3]);
            }
#pragma unroll
            for (int j = 0; j < 8; j++) {
                uint32_t bh0, bl0, bh1, bl1;
                tsplit(*(const float*)(Bs + kt0 * 128 + bcol0[j]), bh0, bl0);
                tsplit(*(const float*)(Bs + kt1 * 128 + bcol1[j]), bh1, bl1);
#pragma unroll
                for (int mi = 0; mi < 2; mi++) {
                    mma_tf32(acc[mi][j], ah[mi], bh0, bh1);
                    mma_tf32(acc[mi][j], ah[mi], bl0, bl1);
                    mma_tf32(acc[mi][j], al[mi], bh0, bh1);
                }
            }
        }
        __syncthreads();
        if (c + NSTAGE < NC && tid == 0) issue(c + NSTAGE);
    }

#pragma unroll
    for (int mi = 0; mi < 2; mi++) {
        const int rA = mbase + mi * 16 + lq;
        const size_t gr0 = rowTile + rA, gr1 = gr0 + 8;
        float s0 = 1.0f, s1 = 1.0f;
        if (MODE == 4) { s0 += ffd[gr0]; s1 += ffd[gr1]; }
#pragma unroll
        for (int j = 0; j < 8; j++) {
            const int col = nbase + j * 8 + lt * 2;
            float o[4];
#pragma unroll
            for (int q = 0; q < 4; q++) {
                const int cc = col + (q & 1);
                float v = acc[mi][j][q];
                if (MODE == 0) v = fmaxf(v + bias1[cc], 0.0f);
                else           v = v * ((q < 2) ? s0 : s1);
                o[q] = v;
            }
            *(float2*)&Cout[gr0 * 128 + col] = make_float2(o[0], o[1]);
            *(float2*)&Cout[gr1 * 128 + col] = make_float2(o[2], o[3]);
        }
    }
}

// ===========================================================================
// Kernel 2: fused GRU gates. One CTA = 128 rows, 512 threads (16 warps, 4x4).
// smem: a tile 64KB | h tile 64KB | weight chunks 2x16KB. 6 K=128 passes:
//   p0: acc_h  = a@Wh0          p1: acc_z  = a@Wz0     p2: acc_z += h@Wz1 -> z
//   p3: acc_r  = a@Wr0          p4: acc_r += h@Wr1 -> r; ro=r*h -> smem(a)
//   p5: acc_h += ro@Wh1 -> h' = relu(acc_h+b)*z + h*(1-z)
// ===========================================================================
#define F_BAR   0u
#define F_A     1024u
#define F_H     (F_A + 65536u)
#define F_W     (F_H + 65536u)
#define F_SMEM  (F_W + 2u * 16384u)    // 164864

__global__ void __launch_bounds__(512, 1)
fused_gate(const __grid_constant__ CUtensorMap mA,
           const __grid_constant__ CUtensorMap mH,
           const __grid_constant__ CUtensorMap mWh0,
           const __grid_constant__ CUtensorMap mWz0,
           const __grid_constant__ CUtensorMap mWz1,
           const __grid_constant__ CUtensorMap mWr0,
           const __grid_constant__ CUtensorMap mWr1,
           const __grid_constant__ CUtensorMap mWh1,
           const float* __restrict__ bz0, const float* __restrict__ bz1,
           const float* __restrict__ br0, const float* __restrict__ br1,
           const float* __restrict__ bh0, const float* __restrict__ bh1,
           float* __restrict__ OutH)
{
    extern __shared__ __align__(1024) char smem[];
    const uint32_t sb = smem_u32(smem);

    const int tid = threadIdx.x, lane = tid & 31, warp = tid >> 5;
    const int wm = warp & 3, wn = warp >> 2;
    const int mbase = wm * 32, nbase = wn * 32;
    const int lq = lane >> 2, lt = lane & 3;
    const int row0 = (int)(blockIdx.x * 128);
    const uint32_t aswz = (uint32_t)lq << 4;

    const CUtensorMap* wmaps[6] = {&mWh0, &mWz0, &mWz1, &mWr0, &mWr1, &mWh1};

    if (tid == 0) {
        mbar_init(sb + F_BAR + 0, 1);
        mbar_init(sb + F_BAR + 8, 1);
        mbar_init(sb + F_BAR + 16, 1);
    }
    __syncthreads();

    auto issueW = [&](int q) {
        const int p = q >> 2, c = q & 3;
        const uint32_t bar = sb + F_BAR + (uint32_t)(q & 1) * 8;
        const uint32_t dst = sb + F_W + (uint32_t)(q & 1) * 16384u;
        mbar_expect(bar, 16384u);
#pragma unroll
        for (int i = 0; i < 4; i++)
            tma2d(dst + i * 4096u, wmaps[p], i * 32, c * 32, bar);
    };

    if (tid == 0) {
        mbar_expect(sb + F_BAR + 16, 131072u);
#pragma unroll
        for (int i = 0; i < 4; i++) {
            tma2d(sb + F_A + i * 16384u, &mA, i * 32, row0, sb + F_BAR + 16);
            tma2d(sb + F_H + i * 16384u, &mH, i * 32, row0, sb + F_BAR + 16);
        }
        issueW(0);
        issueW(1);
    }

    float acc_h[2][4][4], acc_z[2][4][4], acc_r[2][4][4];
#pragma unroll
    for (int mi = 0; mi < 2; mi++)
#pragma unroll
        for (int j = 0; j < 4; j++)
#pragma unroll
            for (int q = 0; q < 4; q++) {
                acc_h[mi][j][q] = 0.0f;
                acc_z[mi][j][q] = 0.0f;
                acc_r[mi][j][q] = 0.0f;
            }

    uint32_t bcol0[4], bcol1[4];
#pragma unroll
    for (int j = 0; j < 4; j++) {
        const int n = nbase + j * 8 + lq;
        const uint32_t nb = (uint32_t)((n & 31) * 4);
        bcol0[j] = ((uint32_t)(n >> 5)) * 4096u + (nb ^ ((uint32_t)lt << 4));
        bcol1[j] = ((uint32_t)(n >> 5)) * 4096u + (nb ^ (((uint32_t)(lt + 4)) << 4));
    }

    // h-tile read address for (local row r with r&7==lq, col c)
    auto h_smem = [&](int r, int c) -> float {
        return *(const float*)(smem + F_H + (uint32_t)(c >> 5) * 16384u
                               + r * 128 + (((uint32_t)((c & 31) * 4)) ^ aswz));
    };

    mbar_wait(sb + F_BAR + 16, 0);   // a & h tiles resident

    auto chunk_mma = [&](float (&acc)[2][4][4], const char* Ab, const char* Wb) {
#pragma unroll
        for (int kk = 0; kk < 32; kk += 8) {
            const int kt0 = kk + lt, kt1 = kt0 + 4;
            uint32_t ah[2][4], al[2][4];
#pragma unroll
            for (int mi = 0; mi < 2; mi++) {
                const int r0 = mbase + mi * 16 + lq, r1 = r0 + 8;
                const uint32_t c0 = ((uint32_t)(kt0 * 4)) ^ aswz;
                const uint32_t c1 = ((uint32_t)(kt1 * 4)) ^ aswz;
                tsplit(*(const float*)(Ab + r0 * 128 + c0), ah[mi][0], al[mi][0]);
                tsplit(*(const float*)(Ab + r1 * 128 + c0), ah[mi][1], al[mi][1]);
                tsplit(*(const float*)(Ab + r0 * 128 + c1), ah[mi][2], al[mi][2]);
                tsplit(*(const float*)(Ab + r1 * 128 + c1), ah[mi][3], al[mi][3]);
            }
#pragma unroll
            for (int j = 0; j < 4; j++) {
                uint32_t bh0, bl0, bh1, bl1;
                tsplit(*(const float*)(Wb + kt0 * 128 + bcol0[j]), bh0, bl0);
                tsplit(*(const float*)(Wb + kt1 * 128 + bcol1[j]), bh1, bl1);
#pragma unroll
                for (int mi = 0; mi < 2; mi++) {
                    mma_tf32(acc[mi][j], ah[mi], bh0, bh1);
                    mma_tf32(acc[mi][j], ah[mi], bl0, bl1);
                    mma_tf32(acc[mi][j], al[mi], bh0, bh1);
                }
            }
        }
    };

#pragma unroll 1
    for (int q = 0; q < 24; ++q) {
        const int p = q >> 2, c = q & 3;
        mbar_wait(sb + F_BAR + (uint32_t)(q & 1) * 8, (uint32_t)((q >> 1) & 1));
        const char* Ab = smem + ((p == 2 || p == 4) ? F_H : F_A) + (uint32_t)c * 16384u;
        const char* Wb = smem + F_W + (uint32_t)(q & 1) * 16384u;
        if (p == 0 || p == 5)      chunk_mma(acc_h, Ab, Wb);
        else if (p <= 2)           chunk_mma(acc_z, Ab, Wb);
        else                       chunk_mma(acc_r, Ab, Wb);

        if (q == 11) {           // z = sigmoid(acc_z + bz)
#pragma unroll
            for (int mi = 0; mi < 2; mi++)
#pragma unroll
                for (int j = 0; j < 4; j++)
#pragma unroll
                    for (int qq = 0; qq < 4; qq++) {
                        const int cc = nbase + j * 8 + lt * 2 + (qq & 1);
                        acc_z[mi][j][qq] = sigmoidf_(acc_z[mi][j][qq] + bz0[cc] + bz1[cc]);
                    }
        }
        if (q == 19) {           // r = sigmoid(acc_r + br); ro = r*h -> smem(A)
#pragma unroll
            for (int mi = 0; mi < 2; mi++) {
                const int r0 = mbase + mi * 16 + lq;
#pragma unroll
                for (int j = 0; j < 4; j++)
#pragma unroll
                    for (int qq = 0; qq < 4; qq++) {
                        const int cc = nbase + j * 8 + lt * 2 + (qq & 1);
                        const int rr = (qq < 2) ? r0 : r0 + 8;
                        const float rv = sigmoidf_(acc_r[mi][j][qq] + br0[cc] + br1[cc]);
                        const float ro = rv * h_smem(rr, cc);
                        *(float*)(smem + F_A + (uint32_t)(cc >> 5) * 16384u
                                  + rr * 128 + (((uint32_t)((cc & 31) * 4)) ^ aswz)) = ro;
                    }
            }
        }
        __syncthreads();
        if (q + 2 < 24 && tid == 0) issueW(q + 2);
    }

    // epilogue: h' = relu(acc_h + bh)*z + h*(1-z)
#pragma unroll
    for (int mi = 0; mi < 2; mi++) {
        const int r0 = mbase + mi * 16 + lq;
        const size_t gr0 = (size_t)row0 + r0, gr1 = gr0 + 8;
#pragma unroll
        for (int j = 0; j < 4; j++) {
            const int col = nbase + j * 8 + lt * 2;
            float o[4];
#pragma unroll
            for (int qq = 0; qq < 4; qq++) {
                const int cc = col + (qq & 1);
                const int rr = (qq < 2) ? r0 : r0 + 8;
                const float zv = acc_z[mi][j][qq];
                const float hp = h_smem(rr, cc);
                o[qq] = fmaxf(acc_h[mi][j][qq] + bh0[cc] + bh1[cc], 0.0f) * zv
                        + hp * (1.0f - zv);
            }
            *(float2*)&OutH[gr0 * 128 + col] = make_float2(o[0], o[1]);
            *(float2*)&OutH[gr1 * 128 + col] = make_float2(o[2], o[3]);
        }
    }
}

// ---------------------------------------------------------------------------
// host side
// ---------------------------------------------------------------------------
typedef CUresult (*pfn_encode_t)(CUtensorMap*, CUtensorMapDataType, cuuint32_t,
                                 void*, const cuuint64_t*, const cuuint64_t*,
                                 const cuuint32_t*, const cuuint32_t*,
                                 CUtensorMapInterleave, CUtensorMapSwizzle,
                                 CUtensorMapL2promotion, CUtensorMapFloatOOBfill);
static pfn_encode_t enc_fn = nullptr;

static void map2d(CUtensorMap* m, const void* ptr, uint64_t d0, uint64_t d1,
                  uint32_t b0, uint32_t b1) {
    cuuint64_t dims[2]    = {d0, d1};
    cuuint64_t strides[1] = {d0 * 4};
    cuuint32_t box[2]     = {b0, b1};
    cuuint32_t es[2]      = {1, 1};
    enc_fn(m, CU_TENSOR_MAP_DATA_TYPE_FLOAT32, 2, (void*)ptr, dims, strides, box, es,
           CU_TENSOR_MAP_INTERLEAVE_NONE, CU_TENSOR_MAP_SWIZZLE_128B,
           CU_TENSOR_MAP_L2_PROMOTION_L2_128B, CU_TENSOR_MAP_FLOAT_OOB_FILL_NONE);
}
static void map3d_sup(CUtensorMap* m, const void* ptr) {
    cuuint64_t dims[3]    = {SEQ, SEQ, BATCH};
    cuuint64_t strides[2] = {(uint64_t)SEQ * 4, (uint64_t)SEQ * SEQ * 4};
    cuuint32_t box[3]     = {32, 128, 1};
    cuuint32_t es[3]      = {1, 1, 1};
    enc_fn(m, CU_TENSOR_MAP_DATA_TYPE_FLOAT32, 3, (void*)ptr, dims, strides, box, es,
           CU_TENSOR_MAP_INTERLEAVE_NONE, CU_TENSOR_MAP_SWIZZLE_128B,
           CU_TENSOR_MAP_L2_PROMOTION_L2_128B, CU_TENSOR_MAP_FLOAT_OOB_FILL_NONE);
}

extern "C" void kernel_launch(void* const* d_in, const int* in_sizes, int n_in,
                              void* d_out, int out_size)
{
    const float* x       = (const float*)d_in[0];
    const float* support = (const float*)d_in[1];
    const float* ffd     = (const float*)d_in[2];
    // d_in[3] = mask (unused by reference)
    const float* We  = (const float*)d_in[4];
    const float* be  = (const float*)d_in[5];
    const float* Wz0 = (const float*)d_in[6];
    const float* bz0 = (const float*)d_in[7];
    const float* Wz1 = (const float*)d_in[8];
    const float* bz1 = (const float*)d_in[9];
    const float* Wr0 = (const float*)d_in[10];
    const float* br0 = (const float*)d_in[11];
    const float* Wr1 = (const float*)d_in[12];
    const float* br1 = (const float*)d_in[13];
    const float* Wh0 = (const float*)d_in[14];
    const float* bh0 = (const float*)d_in[15];
    const float* Wh1 = (const float*)d_in[16];
    const float* bh1 = (const float*)d_in[17];

    float *h, *a;
    cudaGetSymbolAddress((void**)&h, g_h);
    cudaGetSymbolAddress((void**)&a, g_a);

    if (!enc_fn) {
        cudaDriverEntryPointQueryResult qr;
        cudaGetDriverEntryPoint("cuTensorMapEncodeTiled", (void**)&enc_fn,
                                cudaEnableDefault, &qr);
    }

    CUtensorMap m_sup, m_x, m_a, m_h, m_hB;
    CUtensorMap m_We, m_Wz0, m_Wz1, m_Wr0, m_Wr1, m_Wh0, m_Wh1;
    map3d_sup(&m_sup, support);
    map2d(&m_x,  x, DIM, MTOT, 32, 128);
    map2d(&m_a,  a, DIM, MTOT, 32, 128);
    map2d(&m_h,  h, DIM, MTOT, 32, 128);
    map2d(&m_hB, h, DIM, MTOT, 32, 32);
    map2d(&m_We,  We,  DIM, DIM, 32, 32);
    map2d(&m_Wz0, Wz0, DIM, DIM, 32, 32);
    map2d(&m_Wz1, Wz1, DIM, DIM, 32, 32);
    map2d(&m_Wr0, Wr0, DIM, DIM, 32, 32);
    map2d(&m_Wr1, Wr1, DIM, DIM, 32, 32);
    map2d(&m_Wh0, Wh0, DIM, DIM, 32, 32);
    map2d(&m_Wh1, Wh1, DIM, DIM, 32, 32);

    cudaFuncSetAttribute(gemm_tma<0, false, 128>, cudaFuncAttributeMaxDynamicSharedMemorySize, SMEM_BYTES);
    cudaFuncSetAttribute(gemm_tma<4, true, 2048>, cudaFuncAttributeMaxDynamicSharedMemorySize, SMEM_BYTES);
    cudaFuncSetAttribute(fused_gate, cudaFuncAttributeMaxDynamicSharedMemorySize, F_SMEM);

    const dim3 grd_dense(MTOT / 128);          // 256
    const dim3 grd_spmm(SEQ / 128, BATCH);     // (16,16)

    // h = relu(x @ We + be)
    gemm_tma<0, false, 128><<<grd_dense, 256, SMEM_BYTES>>>(m_x, m_We, be, nullptr, h);

    for (int t = 0; t < 2; ++t) {
        // a = (support @ h) * (1 + FFD)
        gemm_tma<4, true, 2048><<<grd_spmm, 256, SMEM_BYTES>>>(m_sup, m_hB, nullptr, ffd, a);
        // fused gates + GRU combine
        float* dst = (t == 1) ? (float*)d_out : h;
        fused_gate<<<grd_dense, 512, F_SMEM>>>(m_a, m_h,
                                               m_Wh0, m_Wz0, m_Wz1, m_Wr0, m_Wr1, m_Wh1,
                                               bz0, bz1, br0, br1, bh0, bh1, dst);
    }
}

// round 9
// speedup vs baseline: 1.8934x; 1.0451x over previous
#include <cuda_runtime.h>
#include <cuda.h>
#include <math.h>
#include <stdint.h>

#define BATCH 16
#define SEQ   2048
#define DIM   128
#define MTOT  (BATCH * SEQ)

// ---------------- scratch (allocation-free device globals) ----------------
__device__ float g_h[MTOT * DIM];
__device__ float g_a[MTOT * DIM];

__device__ __forceinline__ float sigmoidf_(float v) {
    return 1.0f / (1.0f + __expf(-v));
}
__device__ __forceinline__ uint32_t smem_u32(const void* p) {
    uint32_t a;
    asm("{ .reg .u64 t; cvta.to.shared.u64 t, %1; cvt.u32.u64 %0, t; }" : "=r"(a) : "l"(p));
    return a;
}
// truncation split: hi = top tf32 bits, lo = exact remainder (2 ops).
__device__ __forceinline__ void tsplit(float x, uint32_t& hi, uint32_t& lo) {
    hi = __float_as_uint(x) & 0xFFFFE000u;
    lo = __float_as_uint(x - __uint_as_float(hi));
}
__device__ __forceinline__ void mma_tf32(float* d, const uint32_t* a,
                                         uint32_t b0, uint32_t b1) {
    asm volatile("mma.sync.aligned.m16n8k8.row.col.f32.tf32.tf32.f32 "
                 "{%0,%1,%2,%3}, {%4,%5,%6,%7}, {%8,%9}, {%0,%1,%2,%3};"
                 : "+f"(d[0]), "+f"(d[1]), "+f"(d[2]), "+f"(d[3])
                 : "r"(a[0]), "r"(a[1]), "r"(a[2]), "r"(a[3]), "r"(b0), "r"(b1));
}
// ---- TMA + mbarrier ----
__device__ __forceinline__ void tma2d(uint32_t dst, const void* map,
                                      int c0, int c1, uint32_t mbar) {
    asm volatile("cp.async.bulk.tensor.2d.shared::cta.global.tile.mbarrier::complete_tx::bytes "
                 "[%0], [%1, {%2, %3}], [%4];"
                 :: "r"(dst), "l"(map), "r"(c0), "r"(c1), "r"(mbar) : "memory");
}
__device__ __forceinline__ void tma3d(uint32_t dst, const void* map,
                                      int c0, int c1, int c2, uint32_t mbar) {
    asm volatile("cp.async.bulk.tensor.3d.shared::cta.global.tile.mbarrier::complete_tx::bytes "
                 "[%0], [%1, {%2, %3, %4}], [%5];"
                 :: "r"(dst), "l"(map), "r"(c0), "r"(c1), "r"(c2), "r"(mbar) : "memory");
}
__device__ __forceinline__ void mbar_init(uint32_t mbar, uint32_t cnt) {
    asm volatile("mbarrier.init.shared.b64 [%0], %1;" :: "r"(mbar), "r"(cnt) : "memory");
}
__device__ __forceinline__ void mbar_expect(uint32_t mbar, uint32_t bytes) {
    asm volatile("mbarrier.arrive.expect_tx.shared.b64 _, [%0], %1;"
                 :: "r"(mbar), "r"(bytes) : "memory");
}
__device__ __forceinline__ void mbar_wait(uint32_t mbar, uint32_t parity) {
    uint32_t done;
    asm volatile("{\n\t.reg .pred p;\n\t"
                 "mbarrier.try_wait.parity.acquire.cta.shared::cta.b64 p, [%1], %2;\n\t"
                 "selp.b32 %0, 1, 0, p;\n\t}"
                 : "=r"(done) : "r"(mbar), "r"(parity) : "memory");
    while (!done) {
        asm volatile("{\n\t.reg .pred p;\n\t"
                     "mbarrier.try_wait.parity.acquire.cta.shared::cta.b64 p, [%1], %2;\n\t"
                     "selp.b32 %0, 1, 0, p;\n\t}"
                     : "=r"(done) : "r"(mbar), "r"(parity) : "memory");
    }
}

// ===========================================================================
// Kernel 1: encode / spmm (UNCHANGED — proven 260us spmm in rounds 7/8)
// ===========================================================================
#define NSTAGE     3
#define STAGE_B    32768u
#define DATA_OFF   1024u
#define SMEM_BYTES (DATA_OFF + NSTAGE * STAGE_B)

template<int MODE, bool SPMM, int K>
__global__ void __launch_bounds__(256, 2)
gemm_tma(const __grid_constant__ CUtensorMap mA1,
         const __grid_constant__ CUtensorMap mB1,
         const float* __restrict__ bias1,
         const float* __restrict__ ffd, float* __restrict__ Cout)
{
    extern __shared__ __align__(1024) char smem[];
    const uint32_t sb = smem_u32(smem);

    const int tid = threadIdx.x, lane = tid & 31, warp = tid >> 5;
    const int wm = warp & 3, wn = warp >> 2;
    const int mbase = wm * 32, nbase = wn * 64;
    const int lq = lane >> 2, lt = lane & 3;

    const size_t rowTile = SPMM ? ((size_t)blockIdx.y * SEQ + (size_t)blockIdx.x * 128)
                                : ((size_t)blockIdx.x * 128);
    constexpr int NC = K / 32;

    if (tid == 0) {
#pragma unroll
        for (int s = 0; s < NSTAGE; s++) mbar_init(sb + s * 8, 1);
    }
    __syncthreads();

    auto issue = [&](int c) {
        const int s = c % NSTAGE;
        const uint32_t bar  = sb + s * 8;
        const uint32_t dstA = sb + DATA_OFF + s * STAGE_B;
        const uint32_t dstB = dstA + 16384u;
        const int k0 = c * 32;
        mbar_expect(bar, STAGE_B);
        if (SPMM) tma3d(dstA, &mA1, k0, (int)(blockIdx.x * 128), (int)blockIdx.y, bar);
        else      tma2d(dstA, &mA1, k0, (int)(blockIdx.x * 128), bar);
        const int brow = SPMM ? (int)(blockIdx.y * SEQ + k0) : k0;
#pragma unroll
        for (int i = 0; i < 4; i++)
            tma2d(dstB + i * 4096u, &mB1, i * 32, brow, bar);
    };

    float acc[2][8][4];
#pragma unroll
    for (int mi = 0; mi < 2; mi++)
#pragma unroll
        for (int j = 0; j < 8; j++)
#pragma unroll
            for (int q = 0; q < 4; q++) acc[mi][j][q] = 0.0f;

    const uint32_t aswz = (uint32_t)lq << 4;
    uint32_t bcol0[8], bcol1[8];
#pragma unroll
    for (int j = 0; j < 8; j++) {
        const int n  = nbase + j * 8 + lq;
        const uint32_t nb = (uint32_t)((n & 31) * 4);
        bcol0[j] = ((uint32_t)(n >> 5)) * 4096u + (nb ^ ((uint32_t)lt << 4));
        bcol1[j] = ((uint32_t)(n >> 5)) * 4096u + (nb ^ (((uint32_t)(lt + 4)) << 4));
    }

    if (tid == 0) {
        issue(0);
        if (NC > 1) issue(1);
        if (NC > 2) issue(2);
    }

#pragma unroll 1
    for (int c = 0; c < NC; ++c) {
        const int s = c % NSTAGE;
        mbar_wait(sb + s * 8, (uint32_t)((c / NSTAGE) & 1));
        const char* As = smem + DATA_OFF + s * STAGE_B;
        const char* Bs = As + 16384;

#pragma unroll
        for (int kk = 0; kk < 32; kk += 8) {
            const int kt0 = kk + lt, kt1 = kt0 + 4;
            uint32_t ah[2][4], al[2][4];
#pragma unroll
            for (int mi = 0; mi < 2; mi++) {
                const int r0 = mbase + mi * 16 + lq, r1 = r0 + 8;
                const uint32_t c0 = ((uint32_t)(kt0 * 4)) ^ aswz;
                const uint32_t c1 = ((uint32_t)(kt1 * 4)) ^ aswz;
                tsplit(*(const float*)(As + r0 * 128 + c0), ah[mi][0], al[mi][0]);
                tsplit(*(const float*)(As + r1 * 128 + c0), ah[mi][1], al[mi][1]);
                tsplit(*(const float*)(As + r0 * 128 + c1), ah[mi][2], al[mi][2]);
                tsplit(*(const float*)(As + r1 * 128 + c1), ah[mi][3], al[mi][3]);
            }
#pragma unroll
            for (int j = 0; j < 8; j++) {
                uint32_t bh0, bl0, bh1, bl1;
                tsplit(*(const float*)(Bs + kt0 * 128 + bcol0[j]), bh0, bl0);
                tsplit(*(const float*)(Bs + kt1 * 128 + bcol1[j]), bh1, bl1);
#pragma unroll
                for (int mi = 0; mi < 2; mi++) {
                    mma_tf32(acc[mi][j], ah[mi], bh0, bh1);
                    mma_tf32(acc[mi][j], ah[mi], bl0, bl1);
                    mma_tf32(acc[mi][j], al[mi], bh0, bh1);
                }
            }
        }
        __syncthreads();
        if (c + NSTAGE < NC && tid == 0) issue(c + NSTAGE);
    }

#pragma unroll
    for (int mi = 0; mi < 2; mi++) {
        const int rA = mbase + mi * 16 + lq;
        const size_t gr0 = rowTile + rA, gr1 = gr0 + 8;
        float s0 = 1.0f, s1 = 1.0f;
        if (MODE == 4) { s0 += ffd[gr0]; s1 += ffd[gr1]; }
#pragma unroll
        for (int j = 0; j < 8; j++) {
            const int col = nbase + j * 8 + lt * 2;
            float o[4];
#pragma unroll
            for (int q = 0; q < 4; q++) {
                const int cc = col + (q & 1);
                float v = acc[mi][j][q];
                if (MODE == 0) v = fmaxf(v + bias1[cc], 0.0f);
                else           v = v * ((q < 2) ? s0 : s1);
                o[q] = v;
            }
            *(float2*)&Cout[gr0 * 128 + col] = make_float2(o[0], o[1]);
            *(float2*)&Cout[gr1 * 128 + col] = make_float2(o[2], o[3]);
        }
    }
}

// ===========================================================================
// Kernel 2: fused GRU gates v2.1 (race-fixed). 64-row tile, 256 threads,
// 2 CTAs/SM, single live accumulator. Pass order:
//   Wz0(a), Wz1(h) -> z (regs); Wr0(a), Wr1(h) -> ro = r*h -> overwrite H
//   (double-barriered!); Wh0(a), Wh1(ro) -> h' = relu(.+bh)*z + h_gmem*(1-z)
// ===========================================================================
#define G_A    1024u
#define G_H    (G_A + 32768u)
#define G_W    (G_H + 32768u)
#define G_SMEM (G_W + 2u * 16384u)    // 99328

__global__ void __launch_bounds__(256, 2)
fused_gate(const __grid_constant__ CUtensorMap mA,
           const __grid_constant__ CUtensorMap mH,
           const __grid_constant__ CUtensorMap mWz0,
           const __grid_constant__ CUtensorMap mWz1,
           const __grid_constant__ CUtensorMap mWr0,
           const __grid_constant__ CUtensorMap mWr1,
           const __grid_constant__ CUtensorMap mWh0,
           const __grid_constant__ CUtensorMap mWh1,
           const float* __restrict__ bz0, const float* __restrict__ bz1,
           const float* __restrict__ br0, const float* __restrict__ br1,
           const float* __restrict__ bh0, const float* __restrict__ bh1,
           const float* Hg, float* OutH)
{
    extern __shared__ __align__(1024) char smem[];
    const uint32_t sb = smem_u32(smem);

    const int tid = threadIdx.x, lane = tid & 31, warp = tid >> 5;
    const int wm = warp & 1, wn = warp >> 1;
    const int mbase = wm * 32, nbase = wn * 32;
    const int lq = lane >> 2, lt = lane & 3;
    const int row0 = (int)(blockIdx.x * 64);
    const uint32_t aswz = (uint32_t)lq << 4;

    const CUtensorMap* wmaps[6] = {&mWz0, &mWz1, &mWr0, &mWr1, &mWh0, &mWh1};

    if (tid == 0) {
        mbar_init(sb + 0, 1);
        mbar_init(sb + 8, 1);
        mbar_init(sb + 16, 1);
    }
    __syncthreads();

    auto issueW = [&](int q) {
        const int p = q >> 2, c = q & 3;
        const uint32_t bar = sb + (uint32_t)(q & 1) * 8;
        const uint32_t dst = sb + G_W + (uint32_t)(q & 1) * 16384u;
        mbar_expect(bar, 16384u);
#pragma unroll
        for (int i = 0; i < 4; i++)
            tma2d(dst + i * 4096u, wmaps[p], i * 32, c * 32, bar);
    };

    if (tid == 0) {
        mbar_expect(sb + 16, 65536u);
#pragma unroll
        for (int i = 0; i < 4; i++) {
            tma2d(sb + G_A + i * 8192u, &mA, i * 32, row0, sb + 16);
            tma2d(sb + G_H + i * 8192u, &mH, i * 32, row0, sb + 16);
        }
        issueW(0);
        issueW(1);
    }

    float acc[2][4][4], zreg[2][4][4];
#pragma unroll
    for (int mi = 0; mi < 2; mi++)
#pragma unroll
        for (int j = 0; j < 4; j++)
#pragma unroll
            for (int q = 0; q < 4; q++) acc[mi][j][q] = 0.0f;

    uint32_t bcol0[4], bcol1[4];
#pragma unroll
    for (int j = 0; j < 4; j++) {
        const int n = nbase + j * 8 + lq;
        const uint32_t nb = (uint32_t)((n & 31) * 4);
        bcol0[j] = ((uint32_t)(n >> 5)) * 4096u + (nb ^ ((uint32_t)lt << 4));
        bcol1[j] = ((uint32_t)(n >> 5)) * 4096u + (nb ^ (((uint32_t)(lt + 4)) << 4));
    }

    // byte offset (from smem base) of element (row r, col c) in a 64-row tile
    auto toff = [&](uint32_t region, int r, int c) -> uint32_t {
        return region + (uint32_t)(c >> 5) * 8192u + (uint32_t)r * 128u
               + (((uint32_t)((c & 31) * 4)) ^ ((uint32_t)(r & 7) << 4));
    };

    mbar_wait(sb + 16, 0);   // a & h tiles resident

#pragma unroll 1
    for (int q = 0; q < 24; ++q) {
        const int p = q >> 2, c = q & 3;
        mbar_wait(sb + (uint32_t)(q & 1) * 8, (uint32_t)((q >> 1) & 1));
        // A source: passes 1,3 use h; pass 5 uses ro (stored over H); else a
        const uint32_t Areg = (p == 1 || p == 3 || p == 5) ? G_H : G_A;
        const char* Wb = smem + G_W + (uint32_t)(q & 1) * 16384u;

#pragma unroll
        for (int kk = 0; kk < 32; kk += 8) {
            const int kt0 = kk + lt, kt1 = kt0 + 4;
            uint32_t ah[2][4], al[2][4];
#pragma unroll
            for (int mi = 0; mi < 2; mi++) {
                const int r0 = mbase + mi * 16 + lq, r1 = r0 + 8;
                tsplit(*(const float*)(smem + toff(Areg, r0, c * 32 + kt0)), ah[mi][0], al[mi][0]);
                tsplit(*(const float*)(smem + toff(Areg, r1, c * 32 + kt0)), ah[mi][1], al[mi][1]);
                tsplit(*(const float*)(smem + toff(Areg, r0, c * 32 + kt1)), ah[mi][2], al[mi][2]);
                tsplit(*(const float*)(smem + toff(Areg, r1, c * 32 + kt1)), ah[mi][3], al[mi][3]);
            }
#pragma unroll
            for (int j = 0; j < 4; j++) {
                uint32_t bh0, bl0, bh1, bl1;
                tsplit(*(const float*)(Wb + kt0 * 128 + bcol0[j]), bh0, bl0);
                tsplit(*(const float*)(Wb + kt1 * 128 + bcol1[j]), bh1, bl1);
#pragma unroll
                for (int mi = 0; mi < 2; mi++) {
                    mma_tf32(acc[mi][j], ah[mi], bh0, bh1);
                    mma_tf32(acc[mi][j], ah[mi], bl0, bl1);
                    mma_tf32(acc[mi][j], al[mi], bh0, bh1);
                }
            }
        }

        if (q == 7) {       // z = sigmoid(acc + bz); keep in regs; reset acc
#pragma unroll
            for (int mi = 0; mi < 2; mi++)
#pragma unroll
                for (int j = 0; j < 4; j++)
#pragma unroll
                    for (int qq = 0; qq < 4; qq++) {
                        const int cc = nbase + j * 8 + lt * 2 + (qq & 1);
                        zreg[mi][j][qq] = sigmoidf_(acc[mi][j][qq] + bz0[cc] + bz1[cc]);
                        acc[mi][j][qq] = 0.0f;
                    }
        }
        if (q == 15) {
            // RACE FIX: compute ro into acc regs (reads of H), then barrier so
            // ALL warps finish their H reads, then overwrite H, then the
            // end-of-iteration barrier orders writes before pass-5 reads.
#pragma unroll
            for (int mi = 0; mi < 2; mi++) {
                const int r0 = mbase + mi * 16 + lq;
#pragma unroll
                for (int j = 0; j < 4; j++)
#pragma unroll
                    for (int qq = 0; qq < 4; qq++) {
                        const int cc = nbase + j * 8 + lt * 2 + (qq & 1);
                        const int rr = (qq < 2) ? r0 : r0 + 8;
                        const float rv = sigmoidf_(acc[mi][j][qq] + br0[cc] + br1[cc]);
                        const float hv = *(const float*)(smem + toff(G_H, rr, cc));
                        acc[mi][j][qq] = rv * hv;
                    }
            }
            __syncthreads();     // all warps done READING H
#pragma unroll
            for (int mi = 0; mi < 2; mi++) {
                const int r0 = mbase + mi * 16 + lq;
#pragma unroll
                for (int j = 0; j < 4; j++)
#pragma unroll
                    for (int qq = 0; qq < 4; qq++) {
                        const int cc = nbase + j * 8 + lt * 2 + (qq & 1);
                        const int rr = (qq < 2) ? r0 : r0 + 8;
                        *(float*)(smem + toff(G_H, rr, cc)) = acc[mi][j][qq];
                        acc[mi][j][qq] = 0.0f;
                    }
            }
        }
        __syncthreads();
        if (q + 2 < 24 && tid == 0) issueW(q + 2);
    }

    // epilogue: h' = relu(acc + bh)*z + h_gmem*(1-z)
#pragma unroll
    for (int mi = 0; mi < 2; mi++) {
        const int r0 = mbase + mi * 16 + lq;
        const size_t gr0 = (size_t)row0 + r0, gr1 = gr0 + 8;
#pragma unroll
        for (int j = 0; j < 4; j++) {
            const int col = nbase + j * 8 + lt * 2;
            const float2 h0 = *(const float2*)&Hg[gr0 * 128 + col];
            const float2 h1 = *(const float2*)&Hg[gr1 * 128 + col];
            float o[4];
            const float hv[4] = {h0.x, h0.y, h1.x, h1.y};
#pragma unroll
            for (int qq = 0; qq < 4; qq++) {
                const int cc = col + (qq & 1);
                const float zv = zreg[mi][j][qq];
                o[qq] = fmaxf(acc[mi][j][qq] + bh0[cc] + bh1[cc], 0.0f) * zv
                        + hv[qq] * (1.0f - zv);
            }
            *(float2*)&OutH[gr0 * 128 + col] = make_float2(o[0], o[1]);
            *(float2*)&OutH[gr1 * 128 + col] = make_float2(o[2], o[3]);
        }
    }
}

// ---------------------------------------------------------------------------
// host side
// ---------------------------------------------------------------------------
typedef CUresult (*pfn_encode_t)(CUtensorMap*, CUtensorMapDataType, cuuint32_t,
                                 void*, const cuuint64_t*, const cuuint64_t*,
                                 const cuuint32_t*, const cuuint32_t*,
                                 CUtensorMapInterleave, CUtensorMapSwizzle,
                                 CUtensorMapL2promotion, CUtensorMapFloatOOBfill);
static pfn_encode_t enc_fn = nullptr;

static void map2d(CUtensorMap* m, const void* ptr, uint64_t d0, uint64_t d1,
                  uint32_t b0, uint32_t b1) {
    cuuint64_t dims[2]    = {d0, d1};
    cuuint64_t strides[1] = {d0 * 4};
    cuuint32_t box[2]     = {b0, b1};
    cuuint32_t es[2]      = {1, 1};
    enc_fn(m, CU_TENSOR_MAP_DATA_TYPE_FLOAT32, 2, (void*)ptr, dims, strides, box, es,
           CU_TENSOR_MAP_INTERLEAVE_NONE, CU_TENSOR_MAP_SWIZZLE_128B,
           CU_TENSOR_MAP_L2_PROMOTION_L2_128B, CU_TENSOR_MAP_FLOAT_OOB_FILL_NONE);
}
static void map3d_sup(CUtensorMap* m, const void* ptr) {
    cuuint64_t dims[3]    = {SEQ, SEQ, BATCH};
    cuuint64_t strides[2] = {(uint64_t)SEQ * 4, (uint64_t)SEQ * SEQ * 4};
    cuuint32_t box[3]     = {32, 128, 1};
    cuuint32_t es[3]      = {1, 1, 1};
    enc_fn(m, CU_TENSOR_MAP_DATA_TYPE_FLOAT32, 3, (void*)ptr, dims, strides, box, es,
           CU_TENSOR_MAP_INTERLEAVE_NONE, CU_TENSOR_MAP_SWIZZLE_128B,
           CU_TENSOR_MAP_L2_PROMOTION_L2_128B, CU_TENSOR_MAP_FLOAT_OOB_FILL_NONE);
}

extern "C" void kernel_launch(void* const* d_in, const int* in_sizes, int n_in,
                              void* d_out, int out_size)
{
    const float* x       = (const float*)d_in[0];
    const float* support = (const float*)d_in[1];
    const float* ffd     = (const float*)d_in[2];
    // d_in[3] = mask (unused by reference)
    const float* We  = (const float*)d_in[4];
    const float* be  = (const float*)d_in[5];
    const float* Wz0 = (const float*)d_in[6];
    const float* bz0 = (const float*)d_in[7];
    const float* Wz1 = (const float*)d_in[8];
    const float* bz1 = (const float*)d_in[9];
    const float* Wr0 = (const float*)d_in[10];
    const float* br0 = (const float*)d_in[11];
    const float* Wr1 = (const float*)d_in[12];
    const float* br1 = (const float*)d_in[13];
    const float* Wh0 = (const float*)d_in[14];
    const float* bh0 = (const float*)d_in[15];
    const float* Wh1 = (const float*)d_in[16];
    const float* bh1 = (const float*)d_in[17];

    float *h, *a;
    cudaGetSymbolAddress((void**)&h, g_h);
    cudaGetSymbolAddress((void**)&a, g_a);

    if (!enc_fn) {
        cudaDriverEntryPointQueryResult qr;
        cudaGetDriverEntryPoint("cuTensorMapEncodeTiled", (void**)&enc_fn,
                                cudaEnableDefault, &qr);
    }

    CUtensorMap m_sup, m_x, m_hB, m_a64, m_h64;
    CUtensorMap m_We, m_Wz0, m_Wz1, m_Wr0, m_Wr1, m_Wh0, m_Wh1;
    map3d_sup(&m_sup, support);
    map2d(&m_x,   x, DIM, MTOT, 32, 128);
    map2d(&m_hB,  h, DIM, MTOT, 32, 32);
    map2d(&m_a64, a, DIM, MTOT, 32, 64);
    map2d(&m_h64, h, DIM, MTOT, 32, 64);
    map2d(&m_We,  We,  DIM, DIM, 32, 32);
    map2d(&m_Wz0, Wz0, DIM, DIM, 32, 32);
    map2d(&m_Wz1, Wz1, DIM, DIM, 32, 32);
    map2d(&m_Wr0, Wr0, DIM, DIM, 32, 32);
    map2d(&m_Wr1, Wr1, DIM, DIM, 32, 32);
    map2d(&m_Wh0, Wh0, DIM, DIM, 32, 32);
    map2d(&m_Wh1, Wh1, DIM, DIM, 32, 32);

    cudaFuncSetAttribute(gemm_tma<0, false, 128>, cudaFuncAttributeMaxDynamicSharedMemorySize, SMEM_BYTES);
    cudaFuncSetAttribute(gemm_tma<4, true, 2048>, cudaFuncAttributeMaxDynamicSharedMemorySize, SMEM_BYTES);
    cudaFuncSetAttribute(fused_gate, cudaFuncAttributeMaxDynamicSharedMemorySize, G_SMEM);

    const dim3 grd_enc(MTOT / 128);            // 256
    const dim3 grd_spmm(SEQ / 128, BATCH);     // (16,16)
    const dim3 grd_fused(MTOT / 64);           // 512

    // h = relu(x @ We + be)
    gemm_tma<0, false, 128><<<grd_enc, 256, SMEM_BYTES>>>(m_x, m_We, be, nullptr, h);

    for (int t = 0; t < 2; ++t) {
        // a = (support @ h) * (1 + FFD)
        gemm_tma<4, true, 2048><<<grd_spmm, 256, SMEM_BYTES>>>(m_sup, m_hB, nullptr, ffd, a);
        // fused gates + GRU combine
        float* dst = (t == 1) ? (float*)d_out : h;
        fused_gate<<<grd_fused, 256, G_SMEM>>>(m_a64, m_h64,
                                               m_Wz0, m_Wz1, m_Wr0, m_Wr1, m_Wh0, m_Wh1,
                                               bz0, bz1, br0, br1, bh0, bh1, h, dst);
    }
}